// round 6
// baseline (speedup 1.0000x reference)
#include <cuda_runtime.h>
#include <cuda_bf16.h>
#include <cstdint>

// SpatiallyJitterColorChannels: per-(b,c) 2D roll of x[64,3,512,512] fp32.
// out[b,c,h,w] = x[b,c,(h-sh)&511,(w-sw)&511], sh/sw = shifts[b,c,:]-2, |s|<=2.
//
// R6: persistent grid-stride version of the measured-best R2 scheme.
//  - Memory pattern per iteration identical to R2: two adjacent aligned
//    LDG.128 per output quad (duplicate B quad is an L1 hit -> free) +
//    per-plane-uniform register select o in {0..3}. Default caching
//    (R4 .cs / R5 stwt proven neutral; bandwidth is at its ~6.2TB/s ceiling).
//  - 1184 blocks (148 SMs x 8 CTAs) x 256 thr, grid-stride over 12.58M f4:
//    removes per-block dispatch churn and the ragged last-wave tail of the
//    24576-block launch (the only cost component not yet addressed).

#define SHIFT 2
#define NBLOCKS 1184
#define NTHREADS 256

__global__ void __launch_bounds__(NTHREADS) roll2d_kernel(
    const float* __restrict__ x,
    const int*   __restrict__ shifts,   // [B, C, 2] int32 in [0, 2*SHIFT]
    float*       __restrict__ out,
    int n_f4)
{
    const int stride = NBLOCKS * NTHREADS;               // 303104
    float4* out4 = reinterpret_cast<float4*>(out);

    for (int idx = blockIdx.x * NTHREADS + threadIdx.x;
         idx < n_f4; idx += stride)
    {
        int plane  = idx >> 16;                          // / 65536 f4 per plane
        int within = idx & 65535;
        int h      = within >> 7;                        // 128 f4 per row
        int w0     = (within & 127) << 2;

        int sh = shifts[plane * 2 + 0] - SHIFT;
        int sw = shifts[plane * 2 + 1] - SHIFT;

        int qa_off = (sw > 0) ? -4 : 0;
        int o      = (sw > 0) ? 4 - sw : -sw;            // select offset 0..3

        int hs = (h - sh) & 511;
        const float* rowp = x + ((size_t)plane << 18) + (hs << 9);

        int qa = (w0 + qa_off) & 511;                    // aligned, in-row wrap
        int qb = (qa + 4) & 511;
        float4 A = *reinterpret_cast<const float4*>(rowp + qa);
        float4 B = *reinterpret_cast<const float4*>(rowp + qb);

        float4 v;
        switch (o) {   // uniform per plane -> no divergence within warp
            case 0:  v = A; break;
            case 1:  v = make_float4(A.y, A.z, A.w, B.x); break;
            case 2:  v = make_float4(A.z, A.w, B.x, B.y); break;
            default: v = make_float4(A.w, B.x, B.y, B.z); break;
        }
        out4[idx] = v;
    }
}

extern "C" void kernel_launch(void* const* d_in, const int* in_sizes, int n_in,
                              void* d_out, int out_size)
{
    const float* x      = (const float*)d_in[0];
    const int*   shifts = (const int*)d_in[1];
    float*       out    = (float*)d_out;

    int n_f4 = out_size / 4;                 // 12582912
    roll2d_kernel<<<NBLOCKS, NTHREADS>>>(x, shifts, out, n_f4);
}

// round 7
// speedup vs baseline: 1.0638x; 1.0638x over previous
#include <cuda_runtime.h>
#include <cuda_bf16.h>
#include <cstdint>

// SpatiallyJitterColorChannels: per-(b,c) 2D roll of x[64,3,512,512] fp32.
// out[b,c,h,w] = x[b,c,(h-sh)&511,(w-sw)&511], sh/sw = shifts[b,c,:]-2, |s|<=2.
//
// FINAL (R2 configuration, measured best at 63.5us / 6.25TB/s):
//  - Since |sw| <= 2, each output float4 lies within two ADJACENT aligned
//    source quads A,B. Load both with LDG.128 (B of thread t == A of thread
//    t+1 -> L1 hit; DRAM read traffic stays exact) and register-select.
//  - Select pattern o = (sw>0 ? 4-sw : -sw) in {0..3} is uniform per plane:
//    non-divergent switch, pure register moves.
//  - ILP=2, 256 threads, 24576 blocks.
//  - Session evidence: shuffle-dedup (R3), ILP=4 (R4), .cs (R4), stwt (R5),
//    persistent grid-stride (R6) all neutral or worse -> this pattern sits at
//    the mixed read/write HBM ceiling (~89% of spec on required 402MB).

#define SHIFT 2

__global__ void __launch_bounds__(256) roll2d_kernel(
    const float* __restrict__ x,
    const int*   __restrict__ shifts,   // [B, C, 2] int32 in [0, 2*SHIFT]
    float*       __restrict__ out)
{
    int base  = blockIdx.x * 512 + threadIdx.x;   // float4 index of element 0
    int plane = base >> 16;                       // / 65536 f4 per plane

    int sh = shifts[plane * 2 + 0] - SHIFT;
    int sw = shifts[plane * 2 + 1] - SHIFT;

    int qa_off, o;
    if (sw > 0) { qa_off = -4; o = 4 - sw; }      // o in {2,3}
    else        { qa_off = 0;  o = -sw;    }      // o in {0,1,2}

    const float* planep = x + ((size_t)plane << 18);   // * 262144

    float4 A[2], B[2];
    int    oidx[2];

    #pragma unroll
    for (int e = 0; e < 2; e++) {
        int idx    = base + e * 256;
        int within = idx & 65535;
        int h      = within >> 7;            // 128 f4 per row
        int w0     = (within & 127) << 2;    // starting column
        int hs     = (h - sh) & 511;
        const float* rowp = planep + (hs << 9);
        int qa = (w0 + qa_off) & 511;        // aligned quad, never straddles row
        int qb = (qa + 4) & 511;
        A[e] = *reinterpret_cast<const float4*>(rowp + qa);
        B[e] = *reinterpret_cast<const float4*>(rowp + qb);
        oidx[e] = idx;
    }

    #pragma unroll
    for (int e = 0; e < 2; e++) {
        float4 v;
        switch (o) {   // uniform per plane -> no divergence
            case 0:  v = A[e]; break;
            case 1:  v = make_float4(A[e].y, A[e].z, A[e].w, B[e].x); break;
            case 2:  v = make_float4(A[e].z, A[e].w, B[e].x, B[e].y); break;
            default: v = make_float4(A[e].w, B[e].x, B[e].y, B[e].z); break;
        }
        reinterpret_cast<float4*>(out)[oidx[e]] = v;
    }
}

extern "C" void kernel_launch(void* const* d_in, const int* in_sizes, int n_in,
                              void* d_out, int out_size)
{
    const float* x      = (const float*)d_in[0];
    const int*   shifts = (const int*)d_in[1];
    float*       out    = (float*)d_out;

    int n_f4   = out_size / 4;               // 12582912
    int blocks = n_f4 / 512;                 // 24576
    roll2d_kernel<<<blocks, 256>>>(x, shifts, out);
}

// round 8
// speedup vs baseline: 1.0665x; 1.0025x over previous
#include <cuda_runtime.h>
#include <cuda_bf16.h>
#include <cstdint>

// SpatiallyJitterColorChannels: per-(b,c) 2D roll of x[64,3,512,512] fp32.
// out[b,c,h,w] = x[b,c,(h-sh)&511,(w-sw)&511], sh/sw = shifts[b,c,:]-2, |s|<=2.
//
// R8: 256-bit global accesses (sm_100a ld/st.global.v8.f32) on the proven
// dual-adjacent-aligned-chunk + register-select scheme.
//  - Each thread produces one aligned 32B output chunk (8 floats). Its source
//    span [w0-2, w0+9] lies in two adjacent aligned 8-float chunks A,B
//    (B of thread t == A of thread t+1 -> L1 hit; DRAM reads stay exact).
//  - Select offset o = (-sw) mod 8 in {0,1,2,6,7}, uniform per plane ->
//    non-divergent switch with constant shifts (pure register moves).
//  - Halves LSU/L1 wavefronts vs 128-bit version; same bytes in flight.

#define SHIFT 2

__device__ __forceinline__ void ldg256(const float* p, float* r) {
    asm volatile("ld.global.v8.f32 {%0,%1,%2,%3,%4,%5,%6,%7}, [%8];"
                 : "=f"(r[0]), "=f"(r[1]), "=f"(r[2]), "=f"(r[3]),
                   "=f"(r[4]), "=f"(r[5]), "=f"(r[6]), "=f"(r[7])
                 : "l"(p));
}

__device__ __forceinline__ void stg256(float* p, const float* r) {
    asm volatile("st.global.v8.f32 [%0], {%1,%2,%3,%4,%5,%6,%7,%8};"
                 :: "l"(p),
                    "f"(r[0]), "f"(r[1]), "f"(r[2]), "f"(r[3]),
                    "f"(r[4]), "f"(r[5]), "f"(r[6]), "f"(r[7])
                 : "memory");
}

__global__ void __launch_bounds__(256) roll2d_kernel(
    const float* __restrict__ x,
    const int*   __restrict__ shifts,   // [B, C, 2] int32 in [0, 2*SHIFT]
    float*       __restrict__ out)
{
    int idx   = blockIdx.x * 256 + threadIdx.x;  // float8 index
    int plane = idx >> 15;                       // 32768 f8 per plane
    int within = idx & 32767;
    int h      = within >> 6;                    // 64 f8 per row
    int w0     = (within & 63) << 3;             // starting column (mult of 8)

    int sh = shifts[plane * 2 + 0] - SHIFT;
    int sw = shifts[plane * 2 + 1] - SHIFT;

    int qa_off = (sw > 0) ? -8 : 0;
    int o      = (sw > 0) ? 8 - sw : -sw;        // select offset: 0,1,2,6,7

    int hs = (h - sh) & 511;
    const float* rowp = x + ((size_t)plane << 18) + (hs << 9);

    int qa = (w0 + qa_off) & 511;                // aligned 32B chunk, in-row
    int qb = (qa + 8) & 511;

    float C[16];                                 // A (0..7) then B (8..15)
    ldg256(rowp + qa, C);
    ldg256(rowp + qb, C + 8);

    float v[8];
    switch (o) {   // uniform per plane -> no divergence; constant shifts
        case 0: {
            #pragma unroll
            for (int i = 0; i < 8; i++) v[i] = C[i];
        } break;
        case 1: {
            #pragma unroll
            for (int i = 0; i < 8; i++) v[i] = C[1 + i];
        } break;
        case 2: {
            #pragma unroll
            for (int i = 0; i < 8; i++) v[i] = C[2 + i];
        } break;
        case 6: {
            #pragma unroll
            for (int i = 0; i < 8; i++) v[i] = C[6 + i];
        } break;
        default: { // 7
            #pragma unroll
            for (int i = 0; i < 8; i++) v[i] = C[7 + i];
        } break;
    }

    stg256(out + ((size_t)idx << 3), v);
}

extern "C" void kernel_launch(void* const* d_in, const int* in_sizes, int n_in,
                              void* d_out, int out_size)
{
    const float* x      = (const float*)d_in[0];
    const int*   shifts = (const int*)d_in[1];
    float*       out    = (float*)d_out;

    int n_f8   = out_size / 8;               // 6291456
    int blocks = n_f8 / 256;                 // 24576
    roll2d_kernel<<<blocks, 256>>>(x, shifts, out);
}